// round 2
// baseline (speedup 1.0000x reference)
#include <cuda_runtime.h>
#include <stdint.h>

// ===========================================================================
// RLMoERouter: reproduce jax.random.categorical(key(42), prefs/T, (4,8192,2))
// bit-exactly via Threefry-2x32, then REINFORCE bookkeeping.
//
// PRNG variant switches (flip if rel_err is catastrophic):
//   JAX_PARTITIONABLE=1 : jax_threefry_partitionable=True (default in jax>=0.4.36)
//                         counter = (0, flat_index), 32-bit out = o0 ^ o1 (PART_XOR=1)
//                         or o1 only (PART_XOR=0)
//   JAX_PARTITIONABLE=0 : legacy scheme: iota(n) split in halves,
//                         bits[j<n/2]=out0(j, j+n/2), bits[j>=n/2]=out1(j-n/2, j)
// ===========================================================================

#ifndef JAX_PARTITIONABLE
#define JAX_PARTITIONABLE 1
#endif
#ifndef PART_XOR
#define PART_XOR 1
#endif

#define NUM_EXPERTS 64
#define NDRAWS      65536        // 4 * 8192 * 2
#define HALF_DRAWS  32768
#define HALF_N      2097152u     // NDRAWS * 64 / 2

__device__ float d_logits[NUM_EXPERTS];
__device__ float d_probs[NUM_EXPERTS];
__device__ int   d_counts[NUM_EXPERTS];
__device__ int   d_uniform;

// jax.random.key(42) -> threefry key pair (0, 42)
__device__ __forceinline__ uint2 threefry2x32(uint32_t x0, uint32_t x1) {
    const uint32_t ks0 = 0u;
    const uint32_t ks1 = 42u;
    const uint32_t ks2 = 0x1BD11BDAu ^ ks0 ^ ks1;
    x0 += ks0; x1 += ks1;
#define TF_R(r) { x0 += x1; x1 = __funnelshift_l(x1, x1, (r)); x1 ^= x0; }
    TF_R(13) TF_R(15) TF_R(26) TF_R(6)
    x0 += ks1; x1 += ks2 + 1u;
    TF_R(17) TF_R(29) TF_R(16) TF_R(24)
    x0 += ks2; x1 += ks0 + 2u;
    TF_R(13) TF_R(15) TF_R(26) TF_R(6)
    x0 += ks0; x1 += ks1 + 3u;
    TF_R(17) TF_R(29) TF_R(16) TF_R(24)
    x0 += ks1; x1 += ks2 + 4u;
    TF_R(13) TF_R(15) TF_R(26) TF_R(6)
    x0 += ks2; x1 += ks0 + 5u;
#undef TF_R
    return make_uint2(x0, x1);
}

// Monotone uint32 ranking key for (logits[c] + gumbel(bits)).
// Uniform-logits fast path: the u -> -log(-log(u)) map is strictly increasing
// and injective on the 2^23-value grid of (bits>>9), so comparing raw mantissa
// bits reproduces jax's argmax INCLUDING first-index tie-breaking.
__device__ __forceinline__ uint32_t score_key(uint32_t bits, int c, int uni) {
    uint32_t m = bits >> 9;
    if (uni) return m;
    // General path (not taken for this input: prefs == 0):
    // replicate jax.random.uniform(minval=tiny, maxval=1) + gumbel + logits.
    float uf = __uint_as_float(m | 0x3f800000u) - 1.0f;
    const float tiny = 1.17549435082228751e-38f;
    float u = fmaxf(tiny, uf * (1.0f - tiny) + tiny);
    float g = -logf(-logf(u));
    float s = d_logits[c] + g;
    uint32_t su = __float_as_uint(s);
    return (su & 0x80000000u) ? ~su : (su | 0x80000000u);  // order-preserving
}

// Warp-wide argmax, ties -> lowest index (matches jnp.argmax).
__device__ __forceinline__ void warp_argmax(uint32_t& key, int& idx) {
#pragma unroll
    for (int off = 16; off; off >>= 1) {
        uint32_t ok = __shfl_xor_sync(0xffffffffu, key, off);
        int      oi = __shfl_xor_sync(0xffffffffu, idx, off);
        if (ok > key || (ok == key && oi < idx)) { key = ok; idx = oi; }
    }
}

__global__ void setup_kernel(const float* __restrict__ prefs) {
    __shared__ float sl[NUM_EXPERTS];
    __shared__ float se[NUM_EXPERTS];
    int e = threadIdx.x;
    float l = prefs[e] / 1.0f;  // TEMPERATURE = 1.0
    sl[e] = l;
    __syncthreads();
    float mx = -3.402823466e+38f;
    float mn =  3.402823466e+38f;
#pragma unroll 8
    for (int i = 0; i < NUM_EXPERTS; i++) { mx = fmaxf(mx, sl[i]); mn = fminf(mn, sl[i]); }
    float ex = expf(l - mx);
    se[e] = ex;
    __syncthreads();
    float s = 0.0f;
#pragma unroll 8
    for (int i = 0; i < NUM_EXPERTS; i++) s += se[i];
    d_logits[e] = l;
    d_probs[e]  = ex / s;       // exactly 1/64 for zero prefs
    d_counts[e] = 0;            // re-zeroed every call: graph-replay safe
    if (e == 0) d_uniform = (mx == mn) ? 1 : 0;
}

// One warp per draw (partitionable) or per draw-pair (legacy).
__global__ void __launch_bounds__(256) sample_kernel(float* __restrict__ out) {
    int tid  = blockIdx.x * blockDim.x + threadIdx.x;
    int w    = tid >> 5;
    int lane = tid & 31;
    int uni  = d_uniform;

#if JAX_PARTITIONABLE
    int d  = w;                         // draw index in [0, NDRAWS)
    int c0 = lane, c1 = lane + 32;
    uint32_t j0 = (uint32_t)d * 64u + (uint32_t)c0;  // flat elem index, hi=0
    uint2 r0 = threefry2x32(0u, j0);
    uint2 r1 = threefry2x32(0u, j0 + 32u);
#if PART_XOR
    uint32_t b0 = r0.x ^ r0.y;
    uint32_t b1 = r1.x ^ r1.y;
#else
    uint32_t b0 = r0.y;
    uint32_t b1 = r1.y;
#endif
    uint32_t key = score_key(b0, c0, uni);
    int idx = c0;
    { uint32_t k2 = score_key(b1, c1, uni); if (k2 > key) { key = k2; idx = c1; } }
    warp_argmax(key, idx);
    if (lane == 0) {
        out[d]          = (float)idx;
        out[NDRAWS + d] = d_probs[idx];
        atomicAdd(&d_counts[idx], 1);
    }
#else
    // Legacy: thread computes bits for draws d0=w and d1=w+HALF_DRAWS at once
    // (they share threefry calls: counter pair (j, j+HALF_N)).
    int d0 = w, d1 = w + HALF_DRAWS;
    int c0 = lane, c1 = lane + 32;
    uint32_t ja = (uint32_t)d0 * 64u + (uint32_t)c0;
    uint32_t jb = ja + 32u;
    uint2 ra = threefry2x32(ja, ja + HALF_N);  // .x -> (d0,c0), .y -> (d1,c0)
    uint2 rb = threefry2x32(jb, jb + HALF_N);  // .x -> (d0,c1), .y -> (d1,c1)
    uint32_t keyA = score_key(ra.x, c0, uni); int idxA = c0;
    { uint32_t k2 = score_key(rb.x, c1, uni); if (k2 > keyA) { keyA = k2; idxA = c1; } }
    uint32_t keyB = score_key(ra.y, c0, uni); int idxB = c0;
    { uint32_t k2 = score_key(rb.y, c1, uni); if (k2 > keyB) { keyB = k2; idxB = c1; } }
    warp_argmax(keyA, idxA);
    warp_argmax(keyB, idxB);
    if (lane == 0) {
        out[d0]          = (float)idxA;
        out[NDRAWS + d0] = d_probs[idxA];
        atomicAdd(&d_counts[idxA], 1);
        out[d1]          = (float)idxB;
        out[NDRAWS + d1] = d_probs[idxB];
        atomicAdd(&d_counts[idxB], 1);
    }
#endif
}

__global__ void finalize_kernel(const float* __restrict__ prefs, float* __restrict__ out) {
    __shared__ float sc[NUM_EXPERTS];
    __shared__ float sd[NUM_EXPERTS];
    int e = threadIdx.x;
    float c = (float)d_counts[e];
    sc[e] = c;
    __syncthreads();
    float sum = 0.0f;
#pragma unroll 8
    for (int i = 0; i < NUM_EXPERTS; i++) sum += sc[i];
    float mean = sum * (1.0f / NUM_EXPERTS);
    float dev = c - mean;
    sd[e] = dev * dev;
    __syncthreads();
    float ss = 0.0f;
#pragma unroll 8
    for (int i = 0; i < NUM_EXPERTS; i++) ss += sd[i];
    float stdv   = sqrtf(ss / (float)(NUM_EXPERTS - 1));  // ddof=1
    float reward = -(stdv / mean);
    float adv    = reward - 0.0f;                          // baseline = 0
    float freq   = c / sum;
    out[2 * NDRAWS + e] = prefs[e] + 0.1f * adv * (freq - d_probs[e]);
    if (e == 0) out[2 * NDRAWS + NUM_EXPERTS] = 0.0f + 0.1f * adv;  // new_baseline
}

extern "C" void kernel_launch(void* const* d_in, const int* in_sizes, int n_in,
                              void* d_out, int out_size) {
    (void)out_size;
    // inputs: x (unused, 67108864 elems), prefs (64 elems) — pick by size.
    const float* prefs = nullptr;
    for (int i = 0; i < n_in; i++)
        if (in_sizes[i] == NUM_EXPERTS) prefs = (const float*)d_in[i];
    if (!prefs) prefs = (const float*)d_in[n_in - 1];
    float* out = (float*)d_out;

    setup_kernel<<<1, NUM_EXPERTS>>>(prefs);
#if JAX_PARTITIONABLE
    sample_kernel<<<NDRAWS / 8, 256>>>(out);       // 65536 warps, 1 per draw
#else
    sample_kernel<<<HALF_DRAWS / 8, 256>>>(out);   // 32768 warps, 1 per draw-pair
#endif
    finalize_kernel<<<1, NUM_EXPERTS>>>(prefs, out);
}